// round 6
// baseline (speedup 1.0000x reference)
#include <cuda_runtime.h>

// ---------------------------------------------------------------------------
// BLSTM_NMC: Bayesian LSTM, B=512, S=128, H=512, IN=1, OUT=1.
// R5: occupancy-oriented retile of the recurrent step GEMM.
//   grid 512 CTAs (16 batch-tiles x 32 fused-col-tiles), CTA tile 32x64,
//   128 threads, thread tile 4x4, K-chunk 32, double-buffered SMEM,
//   packed fma.rn.f32x2 inner loop, LSTM cell fused in epilogue.
// ---------------------------------------------------------------------------

#define BB 512
#define SS 128
#define HH 512
#define G4 2048

#define TM 32              // batch rows per CTA
#define TNF 64             // fused cols per CTA (16 hidden x 4 gates)
#define KB 32              // k-chunk
#define NCH (HH / KB)      // 16 chunks
#define NTHREADS 128
#define NCTAS 512          // 16 x 32

#define AS 36              // 32 + pad
#define BS 68              // 64 + pad
#define A_BUF (KB * AS)    // 1152 floats
#define B_BUF (KB * BS)    // 2176 floats
#define POOL_FLOATS (2 * A_BUF + 2 * B_BUF)   // 6656 (Sg needs 32*68=2176, fits)

// ---------------- scratch (device globals; no allocation allowed) ----------
__device__ float g_Whh[HH * G4];       // sampled W_hh, [k][n] row-major (4 MB)
__device__ float g_bias[G4];
__device__ float g_Wih[G4];
__device__ float g_xm[SS * BB];        // transposed: xm[s*B + b]
__device__ float g_h[2][BB * HH];      // double-buffered hidden state
__device__ float g_c[BB * HH];         // cell state (in-place per element)

// ---------------- helpers --------------------------------------------------
static __device__ __forceinline__ float softplus_f(float x) {
    return (x > 20.0f) ? x : log1pf(expf(x));
}
static __device__ __forceinline__ float sigm(float x) {
    return __fdividef(1.0f, 1.0f + __expf(-x));
}
static __device__ __forceinline__ float tanh_fast(float x) {
    float e = __expf(2.0f * fabsf(x));       // may be +inf -> r = 1 (correct)
    float r = 1.0f - __fdividef(2.0f, e + 1.0f);
    return copysignf(r, x);
}

static __device__ __forceinline__ unsigned long long pk2(float lo, float hi) {
    unsigned long long r;
    asm("mov.b64 %0, {%1, %2};" : "=l"(r) : "f"(lo), "f"(hi));
    return r;
}
static __device__ __forceinline__ void fma2(unsigned long long& d,
                                            unsigned long long a,
                                            unsigned long long b) {
    asm("fma.rn.f32x2 %0, %1, %2, %0;" : "+l"(d) : "l"(a), "l"(b));
}
static __device__ __forceinline__ void upk2(unsigned long long v, float& lo, float& hi) {
    asm("mov.b64 {%0, %1}, %2;" : "=f"(lo), "=f"(hi) : "l"(v));
}

// ---------------- setup kernels --------------------------------------------
__global__ void k_init(const float* __restrict__ x, const float* __restrict__ mask_in,
                       const float* __restrict__ Wih_mu, const float* __restrict__ Wih_rho,
                       const float* __restrict__ eps_ih,
                       const float* __restrict__ b_mu, const float* __restrict__ b_rho,
                       const float* __restrict__ eps_b) {
    int idx = blockIdx.x * blockDim.x + threadIdx.x;
    if (idx < BB * HH) {
        g_h[0][idx] = 0.0f;
        g_c[idx] = 0.0f;
    }
    if (idx < BB * SS) {
        int b = idx >> 7;                  // x is (B,S) row-major
        int s = idx & (SS - 1);
        g_xm[s * BB + b] = x[idx] * mask_in[idx];
    }
    if (idx < G4) {
        g_Wih[idx]  = Wih_mu[idx] + softplus_f(Wih_rho[idx]) * eps_ih[idx];
        g_bias[idx] = b_mu[idx]   + softplus_f(b_rho[idx])   * eps_b[idx];
    }
}

__global__ void k_sample_whh(const float* __restrict__ mu, const float* __restrict__ rho,
                             const float* __restrict__ eps) {
    int i4 = blockIdx.x * blockDim.x + threadIdx.x;   // float4 index
    if (i4 < (HH * G4) / 4) {
        float4 m = ((const float4*)mu)[i4];
        float4 r = ((const float4*)rho)[i4];
        float4 e = ((const float4*)eps)[i4];
        float4 w;
        w.x = m.x + softplus_f(r.x) * e.x;
        w.y = m.y + softplus_f(r.y) * e.y;
        w.z = m.z + softplus_f(r.z) * e.z;
        w.w = m.w + softplus_f(r.w) * e.w;
        ((float4*)g_Whh)[i4] = w;
    }
}

// ---------------- recurrent step kernel ------------------------------------
__global__ __launch_bounds__(NTHREADS, 4)
void k_step(int t) {
    __shared__ __align__(16) float pool[POOL_FLOATS];
    float* As = pool;                    // [2][KB][AS]  layout [k][m]
    float* Bs = pool + 2 * A_BUF;        // [2][KB][BS]  layout [k][n]

    const int tid = threadIdx.x;
    const int bx  = blockIdx.x;              // 0..511
    const int bm0 = (bx >> 5) * TM;          // 16 batch tiles
    const int hc0 = (bx & 31) * 16;          // 32 hidden-col tiles (16 cols each)

    const float* __restrict__ hin = g_h[t & 1];

    // A (h) loader: thread -> (m = tid&31, kq = tid>>5); 2 float4 along k
    const int am  = tid & 31;
    const int akq = tid >> 5;                // 0..3 -> k offsets kq*4 and kq*4+16
    // B (W_hh) loader: thread -> (n4 = tid&15, kr = tid>>4); 4 float4 at k = kr+8q
    const int bn4 = tid & 15;
    const int bkr = tid >> 4;                // 0..7
    const int bcol = ((bn4 >> 2) << 9) + hc0 + ((bn4 & 3) << 2); // gate*512 + hc0 + j

    const int tm4 = (tid >> 4) << 2;         // 4 batch rows owned
    const int tn4 = (tid & 15) << 2;         // 4 fused cols owned (one gate run)

    unsigned long long acc[4][2];
#pragma unroll
    for (int i = 0; i < 4; i++) { acc[i][0] = 0ull; acc[i][1] = 0ull; }

    float4 ra0, ra1, rb0, rb1, rb2, rb3;

    // ---- load chunk 0 into registers
    {
        const float* ap = &hin[(bm0 + am) * HH + akq * 4];
        ra0 = *(const float4*)(ap);
        ra1 = *(const float4*)(ap + 16);
        const float* bp = &g_Whh[bkr * G4 + bcol];
        rb0 = *(const float4*)(bp);
        rb1 = *(const float4*)(bp + 8 * G4);
        rb2 = *(const float4*)(bp + 16 * G4);
        rb3 = *(const float4*)(bp + 24 * G4);
    }

#define STS_CHUNK(BUFI)                                                          \
    do {                                                                         \
        float* Ab = As + (BUFI) * A_BUF;                                         \
        float* Bb = Bs + (BUFI) * B_BUF;                                         \
        Ab[(akq * 4 + 0) * AS + am] = ra0.x;                                     \
        Ab[(akq * 4 + 1) * AS + am] = ra0.y;                                     \
        Ab[(akq * 4 + 2) * AS + am] = ra0.z;                                     \
        Ab[(akq * 4 + 3) * AS + am] = ra0.w;                                     \
        Ab[(akq * 4 + 16) * AS + am] = ra1.x;                                    \
        Ab[(akq * 4 + 17) * AS + am] = ra1.y;                                    \
        Ab[(akq * 4 + 18) * AS + am] = ra1.z;                                    \
        Ab[(akq * 4 + 19) * AS + am] = ra1.w;                                    \
        *(float4*)&Bb[(bkr)      * BS + bn4 * 4] = rb0;                          \
        *(float4*)&Bb[(bkr + 8)  * BS + bn4 * 4] = rb1;                          \
        *(float4*)&Bb[(bkr + 16) * BS + bn4 * 4] = rb2;                          \
        *(float4*)&Bb[(bkr + 24) * BS + bn4 * 4] = rb3;                          \
    } while (0)

    STS_CHUNK(0);
    __syncthreads();

    for (int ch = 0; ch < NCH; ch++) {
        const int cur = ch & 1;
        if (ch + 1 < NCH) {              // prefetch next chunk into registers
            const int k0 = (ch + 1) * KB;
            const float* ap = &hin[(bm0 + am) * HH + k0 + akq * 4];
            ra0 = *(const float4*)(ap);
            ra1 = *(const float4*)(ap + 16);
            const float* bp = &g_Whh[(k0 + bkr) * G4 + bcol];
            rb0 = *(const float4*)(bp);
            rb1 = *(const float4*)(bp + 8 * G4);
            rb2 = *(const float4*)(bp + 16 * G4);
            rb3 = *(const float4*)(bp + 24 * G4);
        }
        const float* Ab = As + cur * A_BUF;
        const float* Bb = Bs + cur * B_BUF;
#pragma unroll
        for (int kk = 0; kk < KB; kk++) {
            float4 av = *(const float4*)&Ab[kk * AS + tm4];
            float4 bv = *(const float4*)&Bb[kk * BS + tn4];
            unsigned long long bp0 = pk2(bv.x, bv.y);
            unsigned long long bp1 = pk2(bv.z, bv.w);
            float a[4] = {av.x, av.y, av.z, av.w};
#pragma unroll
            for (int i = 0; i < 4; i++) {
                unsigned long long ap2 = pk2(a[i], a[i]);
                fma2(acc[i][0], ap2, bp0);
                fma2(acc[i][1], ap2, bp1);
            }
        }
        if (ch + 1 < NCH) {
            STS_CHUNK(cur ^ 1);
            __syncthreads();
        }
    }

    // ---- epilogue: add input projection + bias, recombine gates via SMEM
    __syncthreads();                       // done with As/Bs; reuse pool as Sg
    float* Sg = pool;                      // [TM][BS], local fused cols 0..63

    const int cbase = ((tn4 >> 4) << 9) + hc0 + (tn4 & 15);   // gate*512 + hc0 + j
    float gw[4], gb[4];
#pragma unroll
    for (int j = 0; j < 4; j++) {
        gw[j] = g_Wih[cbase + j];
        gb[j] = g_bias[cbase + j];
    }
    const float* __restrict__ xmrow = g_xm + t * BB + bm0;
#pragma unroll
    for (int i = 0; i < 4; i++) {
        float xv = xmrow[tm4 + i];
#pragma unroll
        for (int j = 0; j < 2; j++) {
            float lo, hi;
            upk2(acc[i][j], lo, hi);
            Sg[(tm4 + i) * BS + tn4 + 2 * j]     = lo + xv * gw[2 * j]     + gb[2 * j];
            Sg[(tm4 + i) * BS + tn4 + 2 * j + 1] = hi + xv * gw[2 * j + 1] + gb[2 * j + 1];
        }
    }
    __syncthreads();

    // ---- LSTM cell: 32 rows x 16 hidden cols per CTA (512 elems, 4/thread)
    float* __restrict__ hout = g_h[(t + 1) & 1];
#pragma unroll
    for (int e = tid; e < TM * 16; e += NTHREADS) {
        int bl = e >> 4;
        int jh = e & 15;
        float ig = Sg[bl * BS + jh];
        float fg = Sg[bl * BS + 16 + jh];
        float gg = Sg[bl * BS + 32 + jh];
        float og = Sg[bl * BS + 48 + jh];
        int idx = (bm0 + bl) * HH + hc0 + jh;
        float c  = g_c[idx];
        float it = sigm(ig);
        float ft = sigm(fg);
        float gt = tanh_fast(gg);
        float ot = sigm(og);
        float cn = ft * c + it * gt;
        g_c[idx]  = cn;
        hout[idx] = ot * tanh_fast(cn);
    }
#undef STS_CHUNK
}

// ---------------- output head ----------------------------------------------
__global__ void k_final(const float* __restrict__ W_lin, const float* __restrict__ b_lin,
                        const float* __restrict__ mask_out, float* __restrict__ out) {
    int b = blockIdx.x;
    int tid = threadIdx.x;
    const float* hrow = g_h[0] + b * HH;   // after 128 steps h_last is in buf 0
    const float* mrow = mask_out + b * HH;
    float s = 0.0f;
    for (int j = tid; j < HH; j += 128)
        s += hrow[j] * mrow[j] * W_lin[j];
    __shared__ float red[128];
    red[tid] = s;
    __syncthreads();
    for (int off = 64; off > 0; off >>= 1) {
        if (tid < off) red[tid] += red[tid + off];
        __syncthreads();
    }
    if (tid == 0) out[b] = red[0] + b_lin[0];
}

// ---------------- launch ----------------------------------------------------
extern "C" void kernel_launch(void* const* d_in, const int* in_sizes, int n_in,
                              void* d_out, int out_size) {
    const float* x        = (const float*)d_in[0];
    const float* Wih_mu   = (const float*)d_in[1];
    const float* Wih_rho  = (const float*)d_in[2];
    const float* eps_ih   = (const float*)d_in[3];
    const float* Whh_mu   = (const float*)d_in[4];
    const float* Whh_rho  = (const float*)d_in[5];
    const float* eps_hh   = (const float*)d_in[6];
    const float* b_mu     = (const float*)d_in[7];
    const float* b_rho    = (const float*)d_in[8];
    const float* eps_b    = (const float*)d_in[9];
    const float* W_lin    = (const float*)d_in[10];
    const float* b_lin    = (const float*)d_in[11];
    const float* mask_in  = (const float*)d_in[12];
    const float* mask_out = (const float*)d_in[13];
    float* out = (float*)d_out;
    (void)in_sizes; (void)n_in; (void)out_size;

    k_init<<<(BB * HH + 255) / 256, 256>>>(x, mask_in, Wih_mu, Wih_rho, eps_ih,
                                           b_mu, b_rho, eps_b);
    k_sample_whh<<<((HH * G4 / 4) + 255) / 256, 256>>>(Whh_mu, Whh_rho, eps_hh);
    for (int t = 0; t < SS; t++)
        k_step<<<NCTAS, NTHREADS>>>(t);
    k_final<<<BB, 128>>>(W_lin, b_lin, mask_out, out);
}

// round 10
// speedup vs baseline: 2.7235x; 2.7235x over previous
#include <cuda_runtime.h>
#include <cuda_bf16.h>
#include <cstdint>

// ---------------------------------------------------------------------------
// BLSTM_NMC: Bayesian LSTM, B=512, S=128, H=512, IN=1, OUT=1.
// R8: baseline-PTX tensor-core recurrence (mma.sync bf16 hi/lo split).
//   Harness compiles for plain sm_103 (no 'a' feature) -> tcgen05 unavailable;
//   mma.sync.m16n8k16 / ldmatrix / cp.async are baseline and run as HMMA.
//   - W_hh sampled once, split bf16 hi+lo, stored K-major with fused-col
//     permutation p(j,g) = (j>>5)*128 + g*32 + (j&31): each 128-col N-tile
//     holds 32 hidden units x all 4 gates (cell fuses in-CTA).
//   - Step: 128 CTAs x 256 thr, CTA tile 64x128, K=512 in 8 chunks of 64,
//     cp.async double-buffer; warp tile 32x32; 3 mma passes (hh, hl, lh)
//     into fp32 accum; epilogue recombines gates in smem + LSTM cell,
//     emits h as fp32 and bf16 hi/lo for the next step.
// ---------------------------------------------------------------------------

#define BB 512
#define SS 128
#define HH 512
#define G4 2048

#define MT 64              // M rows per CTA
#define NTF 128            // fused cols per CTA
#define KC 64              // k per chunk
#define NCHUNK (HH / KC)   // 8
#define STEP_THREADS 256
#define STEP_CTAS ((BB / MT) * (G4 / NTF))   // 8 * 16 = 128

#define ASTRB 144                       // smem row stride bytes (64 bf16 + 8 pad)
#define A_T (MT * ASTRB)                // 9216 B per A tile
#define B_T (NTF * ASTRB)               // 18432 B per B tile
#define BUFB (2 * A_T + 2 * B_T)        // 55296 B (Ahi,Alo,Bhi,Blo)
#define SMEM_DYN (2 * BUFB)             // 110592 B

// ---------------- scratch ---------------------------------------------------
__device__ __nv_bfloat16 g_Bhi[G4 * HH];   // W_hh hi, [p][k] K-major, permuted
__device__ __nv_bfloat16 g_Blo[G4 * HH];
__device__ __nv_bfloat16 g_hhi[2][BB * HH];
__device__ __nv_bfloat16 g_hlo[2][BB * HH];
__device__ float g_h32[BB * HH];
__device__ float g_c[BB * HH];
__device__ float g_WihP[G4];               // permuted
__device__ float g_biasP[G4];
__device__ float g_xm[SS * BB];            // xm[s*B + b]

// ---------------- scalar helpers -------------------------------------------
static __device__ __forceinline__ float softplus_f(float x) {
    return (x > 20.0f) ? x : log1pf(expf(x));
}
static __device__ __forceinline__ float sigm(float x) {
    return __fdividef(1.0f, 1.0f + __expf(-x));
}
static __device__ __forceinline__ float tanh_fast(float x) {
    float e = __expf(2.0f * fabsf(x));      // may be +inf -> r = 1
    float r = 1.0f - __fdividef(2.0f, e + 1.0f);
    return copysignf(r, x);
}

// ---------------- PTX helpers (baseline sm_80-class only) -------------------
static __device__ __forceinline__ uint32_t smem_u32(const void* p) {
    uint32_t a;
    asm("{ .reg .u64 t; cvta.to.shared.u64 t, %1; cvt.u32.u64 %0, t; }"
        : "=r"(a) : "l"(p));
    return a;
}
static __device__ __forceinline__ void cp16(uint32_t dst, const void* src) {
    asm volatile("cp.async.cg.shared.global [%0], [%1], 16;"
                 :: "r"(dst), "l"(src) : "memory");
}
#define CP_COMMIT() asm volatile("cp.async.commit_group;" ::: "memory")
#define CP_WAIT1()  asm volatile("cp.async.wait_group 1;" ::: "memory")
#define CP_WAIT0()  asm volatile("cp.async.wait_group 0;" ::: "memory")

static __device__ __forceinline__ void ldsm_x4(uint32_t& r0, uint32_t& r1,
                                               uint32_t& r2, uint32_t& r3,
                                               uint32_t addr) {
    asm volatile("ldmatrix.sync.aligned.m8n8.x4.shared.b16 {%0,%1,%2,%3}, [%4];"
                 : "=r"(r0), "=r"(r1), "=r"(r2), "=r"(r3) : "r"(addr));
}
static __device__ __forceinline__ void mma_bf16(float* c, const uint32_t* a,
                                                uint32_t b0, uint32_t b1) {
    asm volatile(
        "mma.sync.aligned.m16n8k16.row.col.f32.bf16.bf16.f32 "
        "{%0,%1,%2,%3}, {%4,%5,%6,%7}, {%8,%9}, {%0,%1,%2,%3};"
        : "+f"(c[0]), "+f"(c[1]), "+f"(c[2]), "+f"(c[3])
        : "r"(a[0]), "r"(a[1]), "r"(a[2]), "r"(a[3]), "r"(b0), "r"(b1));
}

// ---------------- setup kernels --------------------------------------------
__global__ void k_init(const float* __restrict__ x, const float* __restrict__ mask_in,
                       const float* __restrict__ Wih_mu, const float* __restrict__ Wih_rho,
                       const float* __restrict__ eps_ih,
                       const float* __restrict__ b_mu, const float* __restrict__ b_rho,
                       const float* __restrict__ eps_b) {
    int idx = blockIdx.x * blockDim.x + threadIdx.x;
    if (idx < BB * HH) {
        g_hhi[0][idx] = __float2bfloat16(0.0f);
        g_hlo[0][idx] = __float2bfloat16(0.0f);
        g_c[idx] = 0.0f;
    }
    if (idx < BB * SS) {
        int b = idx >> 7;                    // x is (B,S) row-major
        int s = idx & (SS - 1);
        g_xm[s * BB + b] = x[idx] * mask_in[idx];
    }
    if (idx < G4) {
        int j = idx & (HH - 1);
        int g = idx >> 9;
        int p = ((j >> 5) << 7) + (g << 5) + (j & 31);
        g_WihP[p]  = Wih_mu[idx] + softplus_f(Wih_rho[idx]) * eps_ih[idx];
        g_biasP[p] = b_mu[idx]   + softplus_f(b_rho[idx])   * eps_b[idx];
    }
}

// Sample W_hh, split to bf16 hi/lo, store K-major at permuted fused col.
__global__ void k_prep_whh(const float* __restrict__ mu, const float* __restrict__ rho,
                           const float* __restrict__ eps) {
    int idx = blockIdx.x * blockDim.x + threadIdx.x;   // idx = p*HH + k
    if (idx >= G4 * HH) return;
    int k = idx & (HH - 1);
    int p = idx >> 9;
    int blk = p >> 7;
    int g = (p >> 5) & 3;
    int jj = p & 31;
    int n = (g << 9) + (blk << 5) + jj;                // original fused col
    int src = k * G4 + n;                              // W_hh[k][n]
    float w = mu[src] + softplus_f(rho[src]) * eps[src];
    __nv_bfloat16 hi = __float2bfloat16(w);
    __nv_bfloat16 lo = __float2bfloat16(w - __bfloat162float(hi));
    g_Bhi[idx] = hi;
    g_Blo[idx] = lo;
}

// ---------------- recurrent step (mma.sync) ---------------------------------
__global__ __launch_bounds__(STEP_THREADS, 1)
void k_step(int t) {
    extern __shared__ __align__(16) char sm[];
    __shared__ float sWih[NTF];
    __shared__ float sBias[NTF];

    const int tid = threadIdx.x;
    const int wid = tid >> 5;
    const int lid = tid & 31;
    const int bx  = blockIdx.x;                 // 0..127
    const int bm0 = (bx >> 4) * MT;             // 8 M-tiles
    const int ntile = bx & 15;                  // 16 N-tiles
    const int nc0 = ntile * NTF;                // permuted fused col base
    const int hb  = ntile * 32;                 // hidden col base

    if (tid < NTF) {
        sWih[tid]  = g_WihP[nc0 + tid];
        sBias[tid] = g_biasP[nc0 + tid];
    }

    const __nv_bfloat16* __restrict__ Ahi_g = g_hhi[t & 1];
    const __nv_bfloat16* __restrict__ Alo_g = g_hlo[t & 1];

    const uint32_t sb = smem_u32(sm);

    // ---- cp.async loader for chunk c into buffer c&1
    auto load_chunk = [&](int c) {
        const int k0 = c * KC;
        const uint32_t base = sb + (c & 1) * BUFB;
        const uint32_t sAhi = base;
        const uint32_t sAlo = base + A_T;
        const uint32_t sBhi = base + 2 * A_T;
        const uint32_t sBlo = base + 2 * A_T + B_T;
        // A: 64 rows x 8 x 16B
        for (int s = tid; s < 512; s += STEP_THREADS) {
            int r = s >> 3, q = s & 7;
            size_t go = (size_t)(bm0 + r) * HH + k0 + q * 8;
            uint32_t so = r * ASTRB + q * 16;
            cp16(sAhi + so, Ahi_g + go);
            cp16(sAlo + so, Alo_g + go);
        }
        // B: 128 rows x 8 x 16B
        for (int s = tid; s < 1024; s += STEP_THREADS) {
            int r = s >> 3, q = s & 7;
            size_t go = (size_t)(nc0 + r) * HH + k0 + q * 8;
            uint32_t so = r * ASTRB + q * 16;
            cp16(sBhi + so, g_Bhi + go);
            cp16(sBlo + so, g_Blo + go);
        }
        CP_COMMIT();
    };

    // warp layout: 2(M) x 4(N); warp tile 32x32
    const int wm = wid >> 2;
    const int wn = wid & 3;
    // ldmatrix lane offsets
    const int a_row = wm * 32 + (lid & 15);        // + mt*16
    const int a_k8  = (lid >> 4) << 3;
    const int b_nrow = (lid & 7) + ((lid >> 4) << 3);   // + wn*32 + p*16
    const int b_k8   = ((lid >> 3) & 1) << 3;

    float acc[2][4][4];
#pragma unroll
    for (int i = 0; i < 2; i++)
#pragma unroll
        for (int j = 0; j < 4; j++)
#pragma unroll
            for (int v = 0; v < 4; v++) acc[i][j][v] = 0.0f;

    load_chunk(0);

    for (int c = 0; c < NCHUNK; c++) {
        if (c + 1 < NCHUNK) load_chunk(c + 1);
        if (c + 1 < NCHUNK) { CP_WAIT1(); } else { CP_WAIT0(); }
        __syncthreads();

        const uint32_t base = sb + (c & 1) * BUFB;
#pragma unroll
        for (int kk = 0; kk < 4; kk++) {
            const uint32_t kb = (kk * 16 + a_k8) * 2;
            uint32_t ah[2][4], al[2][4];
#pragma unroll
            for (int mt = 0; mt < 2; mt++) {
                uint32_t ad = base + (a_row + mt * 16) * ASTRB + kb;
                ldsm_x4(ah[mt][0], ah[mt][1], ah[mt][2], ah[mt][3], ad);
                ldsm_x4(al[mt][0], al[mt][1], al[mt][2], al[mt][3], ad + A_T);
            }
            const uint32_t kbb = (kk * 16 + b_k8) * 2;
            uint32_t bh[2][4], bl[2][4];
#pragma unroll
            for (int p = 0; p < 2; p++) {
                uint32_t bd = base + 2 * A_T +
                              (wn * 32 + p * 16 + b_nrow) * ASTRB + kbb;
                ldsm_x4(bh[p][0], bh[p][1], bh[p][2], bh[p][3], bd);
                ldsm_x4(bl[p][0], bl[p][1], bl[p][2], bl[p][3], bd + B_T);
            }
#pragma unroll
            for (int mt = 0; mt < 2; mt++)
#pragma unroll
                for (int n8 = 0; n8 < 4; n8++) {
                    const int p = n8 >> 1;
                    const int r = (n8 & 1) * 2;
                    mma_bf16(acc[mt][n8], ah[mt], bh[p][r], bh[p][r + 1]);
                    mma_bf16(acc[mt][n8], ah[mt], bl[p][r], bl[p][r + 1]);
                    mma_bf16(acc[mt][n8], al[mt], bh[p][r], bh[p][r + 1]);
                }
        }
        __syncthreads();
    }

    // ---- epilogue: recombine gates in smem (alias over tile buffers) ------
    float* Sg = (float*)sm;                      // [64][132]
    const int gq  = lid >> 2;
    const int tig = lid & 3;
#pragma unroll
    for (int mt = 0; mt < 2; mt++)
#pragma unroll
        for (int n8 = 0; n8 < 4; n8++) {
            int m = wm * 32 + mt * 16 + gq;
            int n = wn * 32 + n8 * 8 + tig * 2;
            *(float2*)&Sg[m * 132 + n] =
                make_float2(acc[mt][n8][0], acc[mt][n8][1]);
            *(float2*)&Sg[(m + 8) * 132 + n] =
                make_float2(acc[mt][n8][2], acc[mt][n8][3]);
        }
    __syncthreads();

    // ---- LSTM cell: 64 rows x 32 hidden cols (2048 elems, 8/thread) -------
    const int nb = (t + 1) & 1;
    __nv_bfloat16* __restrict__ hhin = g_hhi[nb];
    __nv_bfloat16* __restrict__ hloo = g_hlo[nb];
#pragma unroll
    for (int e = tid; e < MT * 32; e += STEP_THREADS) {
        int m  = e >> 5;
        int jj = e & 31;
        float xv = g_xm[t * BB + bm0 + m];
        float ig = Sg[m * 132 + jj]      + xv * sWih[jj]      + sBias[jj];
        float fg = Sg[m * 132 + 32 + jj] + xv * sWih[32 + jj] + sBias[32 + jj];
        float gg = Sg[m * 132 + 64 + jj] + xv * sWih[64 + jj] + sBias[64 + jj];
        float og = Sg[m * 132 + 96 + jj] + xv * sWih[96 + jj] + sBias[96 + jj];
        size_t idx = (size_t)(bm0 + m) * HH + hb + jj;
        float cv = g_c[idx];
        float it = sigm(ig);
        float ft = sigm(fg);
        float gt = tanh_fast(gg);
        float ot = sigm(og);
        float cn = ft * cv + it * gt;
        g_c[idx] = cn;
        float hv = ot * tanh_fast(cn);
        g_h32[idx] = hv;
        __nv_bfloat16 hi = __float2bfloat16(hv);
        hhin[idx] = hi;
        hloo[idx] = __float2bfloat16(hv - __bfloat162float(hi));
    }
}

// ---------------- output head ----------------------------------------------
__global__ void k_final(const float* __restrict__ W_lin, const float* __restrict__ b_lin,
                        const float* __restrict__ mask_out, float* __restrict__ out) {
    int b = blockIdx.x;
    int tid = threadIdx.x;
    const float* hrow = g_h32 + (size_t)b * HH;
    const float* mrow = mask_out + (size_t)b * HH;
    float s = 0.0f;
    for (int j = tid; j < HH; j += 128)
        s += hrow[j] * mrow[j] * W_lin[j];
    __shared__ float red[128];
    red[tid] = s;
    __syncthreads();
    for (int off = 64; off > 0; off >>= 1) {
        if (tid < off) red[tid] += red[tid + off];
        __syncthreads();
    }
    if (tid == 0) out[b] = red[0] + b_lin[0];
}

// ---------------- launch ----------------------------------------------------
extern "C" void kernel_launch(void* const* d_in, const int* in_sizes, int n_in,
                              void* d_out, int out_size) {
    const float* x        = (const float*)d_in[0];
    const float* Wih_mu   = (const float*)d_in[1];
    const float* Wih_rho  = (const float*)d_in[2];
    const float* eps_ih   = (const float*)d_in[3];
    const float* Whh_mu   = (const float*)d_in[4];
    const float* Whh_rho  = (const float*)d_in[5];
    const float* eps_hh   = (const float*)d_in[6];
    const float* b_mu     = (const float*)d_in[7];
    const float* b_rho    = (const float*)d_in[8];
    const float* eps_b    = (const float*)d_in[9];
    const float* W_lin    = (const float*)d_in[10];
    const float* b_lin    = (const float*)d_in[11];
    const float* mask_in  = (const float*)d_in[12];
    const float* mask_out = (const float*)d_in[13];
    float* out = (float*)d_out;
    (void)in_sizes; (void)n_in; (void)out_size;

    cudaFuncSetAttribute(k_step, cudaFuncAttributeMaxDynamicSharedMemorySize,
                         SMEM_DYN);

    k_init<<<(BB * HH + 255) / 256, 256>>>(x, mask_in, Wih_mu, Wih_rho, eps_ih,
                                           b_mu, b_rho, eps_b);
    k_prep_whh<<<(G4 * HH + 255) / 256, 256>>>(Whh_mu, Whh_rho, eps_hh);
    for (int t = 0; t < SS; t++)
        k_step<<<STEP_CTAS, STEP_THREADS, SMEM_DYN>>>(t);
    k_final<<<BB, 128>>>(W_lin, b_lin, mask_out, out);
}

// round 11
// speedup vs baseline: 2.9404x; 1.0797x over previous
#include <cuda_runtime.h>
#include <cuda_bf16.h>
#include <cstdint>

// ---------------------------------------------------------------------------
// BLSTM_NMC: Bayesian LSTM, B=512, S=128, H=512, IN=1, OUT=1.
// R10: occupancy + dependency fix of the R8 mma.sync recurrence.
//   - CTA tile 64x64 (16 hidden x 4 gates), grid 256, 2 CTAs/SM.
//   - Pass-major mma ordering (hh, hl, lh) -> accumulator reuse distance 4.
//   - W_hh prep rewritten as smem-staged transpose (coalesced both sides).
//   Math identical to R8: bf16 hi/lo split, 3 passes, fp32 accum.
// ---------------------------------------------------------------------------

#define BB 512
#define SS 128
#define HH 512
#define G4 2048

#define MT 64              // M rows per CTA
#define NTF 64             // fused cols per CTA (16 hidden x 4 gates)
#define KC 64              // k per chunk
#define NCHUNK (HH / KC)   // 8
#define STEP_THREADS 256
#define STEP_CTAS ((BB / MT) * (G4 / NTF))   // 8 * 32 = 256

#define ASTRB 144                       // smem row stride bytes (64 bf16 + 16B pad)
#define A_T (MT * ASTRB)                // 9216 B per tile
#define B_T (NTF * ASTRB)               // 9216 B per tile
#define BUFB (2 * A_T + 2 * B_T)        // 36864 B (Ahi,Alo,Bhi,Blo)
#define SMEM_DYN (2 * BUFB)             // 73728 B

// ---------------- scratch ---------------------------------------------------
__device__ __nv_bfloat16 g_Bhi[G4 * HH];   // W_hh hi, [p][k] K-major, permuted
__device__ __nv_bfloat16 g_Blo[G4 * HH];
__device__ __nv_bfloat16 g_hhi[2][BB * HH];
__device__ __nv_bfloat16 g_hlo[2][BB * HH];
__device__ float g_h32[BB * HH];
__device__ float g_c[BB * HH];
__device__ float g_WihP[G4];               // permuted
__device__ float g_biasP[G4];
__device__ float g_xm[SS * BB];            // xm[s*B + b]

// ---------------- scalar helpers -------------------------------------------
static __device__ __forceinline__ float softplus_f(float x) {
    return (x > 20.0f) ? x : log1pf(expf(x));
}
static __device__ __forceinline__ float sigm(float x) {
    return __fdividef(1.0f, 1.0f + __expf(-x));
}
static __device__ __forceinline__ float tanh_fast(float x) {
    float e = __expf(2.0f * fabsf(x));      // may be +inf -> r = 1
    float r = 1.0f - __fdividef(2.0f, e + 1.0f);
    return copysignf(r, x);
}

// ---------------- PTX helpers (baseline sm_80-class only) -------------------
static __device__ __forceinline__ uint32_t smem_u32(const void* p) {
    uint32_t a;
    asm("{ .reg .u64 t; cvta.to.shared.u64 t, %1; cvt.u32.u64 %0, t; }"
        : "=r"(a) : "l"(p));
    return a;
}
static __device__ __forceinline__ void cp16(uint32_t dst, const void* src) {
    asm volatile("cp.async.cg.shared.global [%0], [%1], 16;"
                 :: "r"(dst), "l"(src) : "memory");
}
#define CP_COMMIT() asm volatile("cp.async.commit_group;" ::: "memory")
#define CP_WAIT1()  asm volatile("cp.async.wait_group 1;" ::: "memory")
#define CP_WAIT0()  asm volatile("cp.async.wait_group 0;" ::: "memory")

static __device__ __forceinline__ void ldsm_x4(uint32_t& r0, uint32_t& r1,
                                               uint32_t& r2, uint32_t& r3,
                                               uint32_t addr) {
    asm volatile("ldmatrix.sync.aligned.m8n8.x4.shared.b16 {%0,%1,%2,%3}, [%4];"
                 : "=r"(r0), "=r"(r1), "=r"(r2), "=r"(r3) : "r"(addr));
}
static __device__ __forceinline__ void mma_bf16(float* c, const uint32_t* a,
                                                uint32_t b0, uint32_t b1) {
    asm volatile(
        "mma.sync.aligned.m16n8k16.row.col.f32.bf16.bf16.f32 "
        "{%0,%1,%2,%3}, {%4,%5,%6,%7}, {%8,%9}, {%0,%1,%2,%3};"
        : "+f"(c[0]), "+f"(c[1]), "+f"(c[2]), "+f"(c[3])
        : "r"(a[0]), "r"(a[1]), "r"(a[2]), "r"(a[3]), "r"(b0), "r"(b1));
}

// ---------------- setup kernels --------------------------------------------
__global__ void k_init(const float* __restrict__ x, const float* __restrict__ mask_in,
                       const float* __restrict__ Wih_mu, const float* __restrict__ Wih_rho,
                       const float* __restrict__ eps_ih,
                       const float* __restrict__ b_mu, const float* __restrict__ b_rho,
                       const float* __restrict__ eps_b) {
    int idx = blockIdx.x * blockDim.x + threadIdx.x;
    if (idx < BB * HH) {
        g_hhi[0][idx] = __float2bfloat16(0.0f);
        g_hlo[0][idx] = __float2bfloat16(0.0f);
        g_c[idx] = 0.0f;
    }
    if (idx < BB * SS) {
        int b = idx >> 7;                    // x is (B,S) row-major
        int s = idx & (SS - 1);
        g_xm[s * BB + b] = x[idx] * mask_in[idx];
    }
    if (idx < G4) {
        int j = idx & (HH - 1);
        int g = idx >> 9;
        int p = ((j >> 4) << 6) + (g << 4) + (j & 15);
        g_WihP[p]  = Wih_mu[idx] + softplus_f(Wih_rho[idx]) * eps_ih[idx];
        g_biasP[p] = b_mu[idx]   + softplus_f(b_rho[idx])   * eps_b[idx];
    }
}

// Sample W_hh, split bf16 hi/lo, store K-major at permuted fused col.
// smem-staged transpose: coalesced reads of W[k][n], coalesced 128B writes
// of [p][k] rows. Grid: 8 k-tiles x 128 n-tiles, 256 threads.
__global__ void k_prep_whh(const float* __restrict__ mu, const float* __restrict__ rho,
                           const float* __restrict__ eps) {
    __shared__ float tile[64][17];
    const int k0 = (blockIdx.x >> 7) * 64;
    const int n0 = (blockIdx.x & 127) * 16;
    const int tid = threadIdx.x;
    for (int s = tid; s < 64 * 16; s += 256) {
        int i = s >> 4, j = s & 15;
        int src = (k0 + i) * G4 + n0 + j;
        tile[i][j] = mu[src] + softplus_f(rho[src]) * eps[src];
    }
    __syncthreads();
    for (int s = tid; s < 16 * 64; s += 256) {
        int j = s >> 6, i = s & 63;
        int n = n0 + j;
        int g = n >> 9;
        int jb = n & (HH - 1);
        int p = ((jb >> 4) << 6) + (g << 4) + (jb & 15);
        float w = tile[i][j];
        __nv_bfloat16 hi = __float2bfloat16(w);
        g_Bhi[(size_t)p * HH + k0 + i] = hi;
        g_Blo[(size_t)p * HH + k0 + i] = __float2bfloat16(w - __bfloat162float(hi));
    }
}

// ---------------- recurrent step (mma.sync) ---------------------------------
__global__ __launch_bounds__(STEP_THREADS, 2)
void k_step(int t) {
    extern __shared__ __align__(16) char sm[];
    __shared__ float sWih[NTF];
    __shared__ float sBias[NTF];

    const int tid = threadIdx.x;
    const int wid = tid >> 5;
    const int lid = tid & 31;
    const int bx  = blockIdx.x;                 // 0..255
    const int bm0 = (bx >> 5) * MT;             // 8 M-tiles
    const int ntile = bx & 31;                  // 32 N-tiles
    const int nc0 = ntile * NTF;                // permuted fused col base
    const int hb  = ntile * 16;                 // hidden col base

    if (tid < NTF) {
        sWih[tid]  = g_WihP[nc0 + tid];
        sBias[tid] = g_biasP[nc0 + tid];
    }

    const __nv_bfloat16* __restrict__ Ahi_g = g_hhi[t & 1];
    const __nv_bfloat16* __restrict__ Alo_g = g_hlo[t & 1];

    const uint32_t sb = smem_u32(sm);

    // ---- cp.async loader for chunk c into buffer c&1
    auto load_chunk = [&](int c) {
        const int k0 = c * KC;
        const uint32_t base = sb + (c & 1) * BUFB;
        // A: 64 rows x 8 x 16B (hi+lo)
        for (int s = tid; s < 512; s += STEP_THREADS) {
            int r = s >> 3, q = s & 7;
            size_t go = (size_t)(bm0 + r) * HH + k0 + q * 8;
            uint32_t so = r * ASTRB + q * 16;
            cp16(base + so, Ahi_g + go);
            cp16(base + A_T + so, Alo_g + go);
        }
        // B: 64 rows x 8 x 16B (hi+lo)
        for (int s = tid; s < 512; s += STEP_THREADS) {
            int r = s >> 3, q = s & 7;
            size_t go = (size_t)(nc0 + r) * HH + k0 + q * 8;
            uint32_t so = r * ASTRB + q * 16;
            cp16(base + 2 * A_T + so, g_Bhi + go);
            cp16(base + 2 * A_T + B_T + so, g_Blo + go);
        }
        CP_COMMIT();
    };

    // warp layout: 2(M) x 4(N); warp tile 32x16
    const int wm = wid >> 2;
    const int wn = wid & 3;
    const int a_row = wm * 32 + (lid & 15);                 // + mt*16
    const int a_k8  = (lid >> 4) << 3;
    const int b_row = wn * 16 + (lid & 7) + ((lid >> 4) << 3);
    const int b_k8  = ((lid >> 3) & 1) << 3;

    float acc[2][2][4];
#pragma unroll
    for (int i = 0; i < 2; i++)
#pragma unroll
        for (int j = 0; j < 2; j++)
#pragma unroll
            for (int v = 0; v < 4; v++) acc[i][j][v] = 0.0f;

    load_chunk(0);

    for (int c = 0; c < NCHUNK; c++) {
        if (c + 1 < NCHUNK) load_chunk(c + 1);
        if (c + 1 < NCHUNK) { CP_WAIT1(); } else { CP_WAIT0(); }
        __syncthreads();

        const uint32_t base = sb + (c & 1) * BUFB;
#pragma unroll
        for (int kk = 0; kk < 4; kk++) {
            const uint32_t kb = (kk * 16 + a_k8) * 2;
            uint32_t ah[2][4], al[2][4];
#pragma unroll
            for (int mt = 0; mt < 2; mt++) {
                uint32_t ad = base + (a_row + mt * 16) * ASTRB + kb;
                ldsm_x4(ah[mt][0], ah[mt][1], ah[mt][2], ah[mt][3], ad);
                ldsm_x4(al[mt][0], al[mt][1], al[mt][2], al[mt][3], ad + A_T);
            }
            const uint32_t kbb = (kk * 16 + b_k8) * 2;
            uint32_t bh[4], bl[4];
            {
                uint32_t bd = base + 2 * A_T + b_row * ASTRB + kbb;
                ldsm_x4(bh[0], bh[1], bh[2], bh[3], bd);
                ldsm_x4(bl[0], bl[1], bl[2], bl[3], bd + B_T);
            }
            // pass-major: consecutive mmas hit different accumulators
#pragma unroll
            for (int mt = 0; mt < 2; mt++)
#pragma unroll
                for (int n8 = 0; n8 < 2; n8++)
                    mma_bf16(acc[mt][n8], ah[mt], bh[2 * n8], bh[2 * n8 + 1]);
#pragma unroll
            for (int mt = 0; mt < 2; mt++)
#pragma unroll
                for (int n8 = 0; n8 < 2; n8++)
                    mma_bf16(acc[mt][n8], ah[mt], bl[2 * n8], bl[2 * n8 + 1]);
#pragma unroll
            for (int mt = 0; mt < 2; mt++)
#pragma unroll
                for (int n8 = 0; n8 < 2; n8++)
                    mma_bf16(acc[mt][n8], al[mt], bh[2 * n8], bh[2 * n8 + 1]);
        }
        __syncthreads();
    }

    // ---- epilogue: recombine gates in smem (alias over tile buffers) ------
    float* Sg = (float*)sm;                      // [64][68]
    const int gq  = lid >> 2;
    const int tig = lid & 3;
#pragma unroll
    for (int mt = 0; mt < 2; mt++)
#pragma unroll
        for (int n8 = 0; n8 < 2; n8++) {
            int m = wm * 32 + mt * 16 + gq;
            int n = wn * 16 + n8 * 8 + tig * 2;
            *(float2*)&Sg[m * 68 + n] =
                make_float2(acc[mt][n8][0], acc[mt][n8][1]);
            *(float2*)&Sg[(m + 8) * 68 + n] =
                make_float2(acc[mt][n8][2], acc[mt][n8][3]);
        }
    __syncthreads();

    // ---- LSTM cell: 64 rows x 16 hidden cols (1024 elems, 4/thread) -------
    const int nb = (t + 1) & 1;
    __nv_bfloat16* __restrict__ hhin = g_hhi[nb];
    __nv_bfloat16* __restrict__ hloo = g_hlo[nb];
#pragma unroll
    for (int e = tid; e < MT * 16; e += STEP_THREADS) {
        int m  = e >> 4;
        int jj = e & 15;
        float xv = g_xm[t * BB + bm0 + m];
        float ig = Sg[m * 68 + jj]      + xv * sWih[jj]      + sBias[jj];
        float fg = Sg[m * 68 + 16 + jj] + xv * sWih[16 + jj] + sBias[16 + jj];
        float gg = Sg[m * 68 + 32 + jj] + xv * sWih[32 + jj] + sBias[32 + jj];
        float og = Sg[m * 68 + 48 + jj] + xv * sWih[48 + jj] + sBias[48 + jj];
        size_t idx = (size_t)(bm0 + m) * HH + hb + jj;
        float cv = g_c[idx];
        float it = sigm(ig);
        float ft = sigm(fg);
        float gt = tanh_fast(gg);
        float ot = sigm(og);
        float cn = ft * cv + it * gt;
        g_c[idx] = cn;
        float hv = ot * tanh_fast(cn);
        g_h32[idx] = hv;
        __nv_bfloat16 hi = __float2bfloat16(hv);
        hhin[idx] = hi;
        hloo[idx] = __float2bfloat16(hv - __bfloat162float(hi));
    }
}

// ---------------- output head ----------------------------------------------
__global__ void k_final(const float* __restrict__ W_lin, const float* __restrict__ b_lin,
                        const float* __restrict__ mask_out, float* __restrict__ out) {
    int b = blockIdx.x;
    int tid = threadIdx.x;
    const float* hrow = g_h32 + (size_t)b * HH;
    const float* mrow = mask_out + (size_t)b * HH;
    float s = 0.0f;
    for (int j = tid; j < HH; j += 128)
        s += hrow[j] * mrow[j] * W_lin[j];
    __shared__ float red[128];
    red[tid] = s;
    __syncthreads();
    for (int off = 64; off > 0; off >>= 1) {
        if (tid < off) red[tid] += red[tid + off];
        __syncthreads();
    }
    if (tid == 0) out[b] = red[0] + b_lin[0];
}

// ---------------- launch ----------------------------------------------------
extern "C" void kernel_launch(void* const* d_in, const int* in_sizes, int n_in,
                              void* d_out, int out_size) {
    const float* x        = (const float*)d_in[0];
    const float* Wih_mu   = (const float*)d_in[1];
    const float* Wih_rho  = (const float*)d_in[2];
    const float* eps_ih   = (const float*)d_in[3];
    const float* Whh_mu   = (const float*)d_in[4];
    const float* Whh_rho  = (const float*)d_in[5];
    const float* eps_hh   = (const float*)d_in[6];
    const float* b_mu     = (const float*)d_in[7];
    const float* b_rho    = (const float*)d_in[8];
    const float* eps_b    = (const float*)d_in[9];
    const float* W_lin    = (const float*)d_in[10];
    const float* b_lin    = (const float*)d_in[11];
    const float* mask_in  = (const float*)d_in[12];
    const float* mask_out = (const float*)d_in[13];
    float* out = (float*)d_out;
    (void)in_sizes; (void)n_in; (void)out_size;

    cudaFuncSetAttribute(k_step, cudaFuncAttributeMaxDynamicSharedMemorySize,
                         SMEM_DYN);

    k_init<<<(BB * HH + 255) / 256, 256>>>(x, mask_in, Wih_mu, Wih_rho, eps_ih,
                                           b_mu, b_rho, eps_b);
    k_prep_whh<<<(8 * 128), 256>>>(Whh_mu, Whh_rho, eps_hh);
    for (int t = 0; t < SS; t++)
        k_step<<<STEP_CTAS, STEP_THREADS, SMEM_DYN>>>(t);
    k_final<<<BB, 128>>>(W_lin, b_lin, mask_out, out);
}